// round 1
// baseline (speedup 1.0000x reference)
#include <cuda_runtime.h>

// Top-K (K=5000) of 50M floats, output values ordered by original index.
// Strategy: 12-bit key histogram -> threshold bin -> compact candidates ->
// exact pairwise rank/order on the tiny candidate set.

#define BINS 4096
#define CAP  262144
#define FULLMASK 0xFFFFFFFFu
#define CHUNK 256

__device__ unsigned g_hist[BINS];
__device__ unsigned g_binb;
__device__ unsigned g_cand_count;
__device__ float    g_cand_val[CAP];
__device__ int      g_cand_idx[CAP];
__device__ int      g_rank[CAP];
__device__ int      g_pos[CAP];

__device__ __forceinline__ unsigned fkey(float f) {
    unsigned u = __float_as_uint(f);
    return (u & 0x80000000u) ? ~u : (u | 0x80000000u);
}

__global__ void init_kernel() {
    int t = blockIdx.x * blockDim.x + threadIdx.x;
    int stride = gridDim.x * blockDim.x;
    for (int i = t; i < BINS; i += stride) g_hist[i] = 0;
    for (int i = t; i < CAP; i += stride) { g_rank[i] = 0; g_pos[i] = 0; }
    if (t == 0) g_cand_count = 0;
}

__global__ void hist_kernel(const float4* __restrict__ x4, int n4,
                            const float* __restrict__ x, int n) {
    __shared__ unsigned sh[BINS];
    for (int i = threadIdx.x; i < BINS; i += blockDim.x) sh[i] = 0;
    __syncthreads();
    int t = blockIdx.x * blockDim.x + threadIdx.x;
    int stride = gridDim.x * blockDim.x;
    for (int i = t; i < n4; i += stride) {
        float4 v = x4[i];
        atomicAdd(&sh[fkey(v.x) >> 20], 1u);
        atomicAdd(&sh[fkey(v.y) >> 20], 1u);
        atomicAdd(&sh[fkey(v.z) >> 20], 1u);
        atomicAdd(&sh[fkey(v.w) >> 20], 1u);
    }
    // scalar tail (n % 4 elements)
    if (blockIdx.x == 0 && (int)threadIdx.x < (n - n4 * 4)) {
        atomicAdd(&sh[fkey(x[n4 * 4 + threadIdx.x]) >> 20], 1u);
    }
    __syncthreads();
    for (int i = threadIdx.x; i < BINS; i += blockDim.x) {
        unsigned c = sh[i];
        if (c) atomicAdd(&g_hist[i], c);
    }
}

// One block, 1024 threads: suffix-sum the 4096-bin histogram and find the bin
// containing the K-th largest element.
__global__ void scan_hist_kernel(int K) {
    __shared__ unsigned h[BINS];
    __shared__ unsigned pa[1024];
    __shared__ unsigned pb[1024];
    int t = threadIdx.x;
    for (int i = t; i < BINS; i += 1024) h[i] = g_hist[i];
    __syncthreads();
    unsigned lp = h[4 * t] + h[4 * t + 1] + h[4 * t + 2] + h[4 * t + 3];
    pa[t] = lp;
    __syncthreads();
    unsigned* cur = pa;
    unsigned* nxt = pb;
    for (int off = 1; off < 1024; off <<= 1) {
        unsigned v = cur[t] + ((t + off < 1024) ? cur[t + off] : 0u);
        nxt[t] = v;
        __syncthreads();
        unsigned* tmp = cur; cur = nxt; nxt = tmp;
    }
    unsigned suffIncl  = cur[t];        // sum of parts t..1023
    unsigned suffAfter = suffIncl - lp; // sum of parts t+1..1023
    unsigned cum = suffAfter;           // cum(bin 4t+4)
    #pragma unroll
    for (int j = 3; j >= 0; j--) {
        unsigned c = h[4 * t + j];
        unsigned cumj = cum + c;        // count of elements in bins >= 4t+j
        if (cumj >= (unsigned)K && cum < (unsigned)K) g_binb = (unsigned)(4 * t + j);
        cum = cumj;
    }
}

__global__ void compact_kernel(const float4* __restrict__ x4, int n4,
                               const float* __restrict__ x, int n) {
    unsigned b = g_binb;
    int t = blockIdx.x * blockDim.x + threadIdx.x;
    int stride = gridDim.x * blockDim.x;
    int iters = (n4 + stride - 1) / stride;
    int lane = threadIdx.x & 31;
    for (int it = 0; it < iters; it++) {
        int i = t + it * stride;
        bool valid = i < n4;
        float4 v;
        v.x = v.y = v.z = v.w = 0.0f;
        if (valid) v = x4[i];
        bool p0 = valid && ((fkey(v.x) >> 20) >= b);
        bool p1 = valid && ((fkey(v.y) >> 20) >= b);
        bool p2 = valid && ((fkey(v.z) >> 20) >= b);
        bool p3 = valid && ((fkey(v.w) >> 20) >= b);
        int cnt = (int)p0 + (int)p1 + (int)p2 + (int)p3;
        unsigned act = __ballot_sync(FULLMASK, cnt > 0);
        if (!act) continue;
        // warp-inclusive prefix sum of cnt
        int pre = cnt;
        #pragma unroll
        for (int o = 1; o < 32; o <<= 1) {
            int u = __shfl_up_sync(FULLMASK, pre, o);
            if (lane >= o) pre += u;
        }
        int tot = __shfl_sync(FULLMASK, pre, 31);
        int base = 0;
        if (lane == 31) base = (int)atomicAdd(&g_cand_count, (unsigned)tot);
        base = __shfl_sync(FULLMASK, base, 31);
        int off = base + pre - cnt;
        int bi = i * 4;
        if (p0 && off < CAP) { g_cand_val[off] = v.x; g_cand_idx[off] = bi;     off++; }
        if (p1 && off < CAP) { g_cand_val[off] = v.y; g_cand_idx[off] = bi + 1; off++; }
        if (p2 && off < CAP) { g_cand_val[off] = v.z; g_cand_idx[off] = bi + 2; off++; }
        if (p3 && off < CAP) { g_cand_val[off] = v.w; g_cand_idx[off] = bi + 3; off++; }
    }
    // scalar tail
    if (blockIdx.x == 0 && (int)threadIdx.x < (n - n4 * 4)) {
        int idx = n4 * 4 + threadIdx.x;
        float f = x[idx];
        if ((fkey(f) >> 20) >= b) {
            unsigned off = atomicAdd(&g_cand_count, 1u);
            if (off < CAP) { g_cand_val[off] = f; g_cand_idx[off] = idx; }
        }
    }
}

// rank[i] = #{j : (key_j > key_i) || (key_j == key_i && idx_j < idx_i)}
// Strict total order (idx unique) -> exactly K candidates have rank < K.
__global__ void rank_kernel() {
    unsigned cc = g_cand_count;
    int M = (int)(cc < (unsigned)CAP ? cc : (unsigned)CAP);
    int nch = (M + CHUNK - 1) / CHUNK;
    long long total = (long long)M * nch;
    long long t = (long long)blockIdx.x * blockDim.x + threadIdx.x;
    long long stride = (long long)gridDim.x * blockDim.x;
    for (long long s = t; s < total; s += stride) {
        int i = (int)(s / nch);
        int c = (int)(s % nch);
        unsigned ki = fkey(g_cand_val[i]);
        int ii = g_cand_idx[i];
        int j0 = c * CHUNK;
        int j1 = j0 + CHUNK; if (j1 > M) j1 = M;
        int r = 0;
        for (int j = j0; j < j1; j++) {
            unsigned kj = fkey(g_cand_val[j]);
            int ij = g_cand_idx[j];
            r += (int)((kj > ki) || (kj == ki && ij < ii));
        }
        if (r) atomicAdd(&g_rank[i], r);
    }
}

// pos[i] = #{j : selected(j) && idx_j < idx_i}, selected(j) = rank[j] < K
__global__ void pos_kernel(int K) {
    unsigned cc = g_cand_count;
    int M = (int)(cc < (unsigned)CAP ? cc : (unsigned)CAP);
    int nch = (M + CHUNK - 1) / CHUNK;
    long long total = (long long)M * nch;
    long long t = (long long)blockIdx.x * blockDim.x + threadIdx.x;
    long long stride = (long long)gridDim.x * blockDim.x;
    for (long long s = t; s < total; s += stride) {
        int i = (int)(s / nch);
        int c = (int)(s % nch);
        int ii = g_cand_idx[i];
        int j0 = c * CHUNK;
        int j1 = j0 + CHUNK; if (j1 > M) j1 = M;
        int r = 0;
        for (int j = j0; j < j1; j++) {
            r += (int)((g_rank[j] < K) && (g_cand_idx[j] < ii));
        }
        if (r) atomicAdd(&g_pos[i], r);
    }
}

__global__ void write_kernel(float* __restrict__ out, int K) {
    unsigned cc = g_cand_count;
    int M = (int)(cc < (unsigned)CAP ? cc : (unsigned)CAP);
    int t = blockIdx.x * blockDim.x + threadIdx.x;
    int stride = gridDim.x * blockDim.x;
    for (int i = t; i < M; i += stride) {
        if (g_rank[i] < K) out[g_pos[i]] = g_cand_val[i];
    }
}

extern "C" void kernel_launch(void* const* d_in, const int* in_sizes, int n_in,
                              void* d_out, int out_size) {
    const float* x = (const float*)d_in[0];
    int n = in_sizes[0];
    int n4 = n / 4;
    const float4* x4 = (const float4*)x;
    int K = out_size;   // 5000
    float* out = (float*)d_out;

    init_kernel<<<256, 256>>>();
    hist_kernel<<<296, 1024>>>(x4, n4, x, n);
    scan_hist_kernel<<<1, 1024>>>(K);
    compact_kernel<<<296, 1024>>>(x4, n4, x, n);
    rank_kernel<<<1024, 256>>>();
    pos_kernel<<<1024, 256>>>(K);
    write_kernel<<<64, 256>>>(out, K);
}

// round 2
// speedup vs baseline: 11.0522x; 11.0522x over previous
#include <cuda_runtime.h>

// Top-K (K=5000) of 50M floats, values output in original-index order.
//
// Fast path: single streaming pass compacts x >= 3.2 (~34K candidates for
// N(0,1)); exact 32-bit radix refinement (12+12+8) on candidates in one
// block finds the exact K-th key + index tie-break; compact selected K;
// small kernel orders by original index.
//
// Correctness fallback (flag-guarded, no-op normally): if speculation
// captured < K or overflowed, do hist -> bin threshold -> re-compact.

#define CAP      (1 << 21)          // candidate capacity (2M)
#define TIECAP   65536
#define BINS     4096
#define SPEC_VAL 3.2f
#define FULLMASK 0xFFFFFFFFu

__device__ unsigned g_hist[BINS];
__device__ unsigned g_cand_count;
__device__ unsigned g_fallback;
__device__ unsigned g_binb;
__device__ float    g_cand_val[CAP];
__device__ int      g_cand_idx[CAP];
__device__ int      g_tie_idx[TIECAP];
__device__ unsigned g_sel_count;
__device__ float    g_sel_val[8192];
__device__ int      g_sel_idx[8192];

__device__ __forceinline__ unsigned fkey(float f) {
    unsigned u = __float_as_uint(f);
    return (u & 0x80000000u) ? ~u : (u | 0x80000000u);
}

// ---------------------------------------------------------------- init
__global__ void init_kernel() {
    int t = threadIdx.x;
    for (int i = t; i < BINS; i += 1024) g_hist[i] = 0;
    if (t == 0) { g_cand_count = 0; g_fallback = 0; g_sel_count = 0; g_binb = 0; }
}

// ------------------------------------------------- pass 1: speculative compact
__global__ void spec_compact_kernel(const float4* __restrict__ x4, int n4,
                                    const float* __restrict__ x, int n) {
    int t = blockIdx.x * blockDim.x + threadIdx.x;
    int stride = gridDim.x * blockDim.x;
    int lane = threadIdx.x & 31;
    for (int i = t; i < n4; i += stride) {
        float4 v = x4[i];
        bool p0 = v.x >= SPEC_VAL;
        bool p1 = v.y >= SPEC_VAL;
        bool p2 = v.z >= SPEC_VAL;
        bool p3 = v.w >= SPEC_VAL;
        int cnt = (int)p0 + (int)p1 + (int)p2 + (int)p3;
        if (!__ballot_sync(FULLMASK, cnt > 0)) continue;
        int pre = cnt;
        #pragma unroll
        for (int o = 1; o < 32; o <<= 1) {
            int u = __shfl_up_sync(FULLMASK, pre, o);
            if (lane >= o) pre += u;
        }
        int tot = __shfl_sync(FULLMASK, pre, 31);
        int base = 0;
        if (lane == 31) base = (int)atomicAdd(&g_cand_count, (unsigned)tot);
        base = __shfl_sync(FULLMASK, base, 31);
        int off = base + pre - cnt;
        int bi = i * 4;
        if (p0) { if (off < CAP) { g_cand_val[off] = v.x; g_cand_idx[off] = bi;     } off++; }
        if (p1) { if (off < CAP) { g_cand_val[off] = v.y; g_cand_idx[off] = bi + 1; } off++; }
        if (p2) { if (off < CAP) { g_cand_val[off] = v.z; g_cand_idx[off] = bi + 2; } off++; }
        if (p3) { if (off < CAP) { g_cand_val[off] = v.w; g_cand_idx[off] = bi + 3; } off++; }
    }
    if (blockIdx.x == 0 && (int)threadIdx.x < (n - n4 * 4)) {
        int idx = n4 * 4 + threadIdx.x;
        float f = x[idx];
        if (f >= SPEC_VAL) {
            unsigned off = atomicAdd(&g_cand_count, 1u);
            if (off < CAP) { g_cand_val[off] = f; g_cand_idx[off] = idx; }
        }
    }
}

// ------------------------------------------------- check speculation
__global__ void check_kernel(int K) {
    unsigned c = g_cand_count;
    if (c >= (unsigned)K && c <= (unsigned)CAP) {
        g_fallback = 0;
    } else {
        g_fallback = 1;
        g_cand_count = 0;
    }
}

// ------------------------------------------------- fallback: full histogram
__global__ void fb_hist_kernel(const float4* __restrict__ x4, int n4,
                               const float* __restrict__ x, int n) {
    if (g_fallback == 0) return;
    __shared__ unsigned sh[BINS];
    for (int i = threadIdx.x; i < BINS; i += blockDim.x) sh[i] = 0;
    __syncthreads();
    int t = blockIdx.x * blockDim.x + threadIdx.x;
    int stride = gridDim.x * blockDim.x;
    for (int i = t; i < n4; i += stride) {
        float4 v = x4[i];
        atomicAdd(&sh[fkey(v.x) >> 20], 1u);
        atomicAdd(&sh[fkey(v.y) >> 20], 1u);
        atomicAdd(&sh[fkey(v.z) >> 20], 1u);
        atomicAdd(&sh[fkey(v.w) >> 20], 1u);
    }
    if (blockIdx.x == 0 && (int)threadIdx.x < (n - n4 * 4)) {
        atomicAdd(&sh[fkey(x[n4 * 4 + threadIdx.x]) >> 20], 1u);
    }
    __syncthreads();
    for (int i = threadIdx.x; i < BINS; i += blockDim.x) {
        unsigned c = sh[i];
        if (c) atomicAdd(&g_hist[i], c);
    }
}

// suffix-select over smem hist: find bin B with cnt_ge(B) >= R > cnt_ge(B+1).
// outB/outR are smem scalars. 1024 threads. NB must be 256 or 4096.
template <int NB>
__device__ void suffix_select(unsigned* h, unsigned* scan, unsigned R,
                              unsigned* outB, unsigned* outR) {
    const int BPT = (NB >= 1024) ? NB / 1024 : 1;
    int t = threadIdx.x;
    unsigned local = 0;
    if (NB >= 1024) {
        #pragma unroll
        for (int j = 0; j < BPT; j++) local += h[t * BPT + j];
    } else {
        local = (t < NB) ? h[t] : 0u;
    }
    scan[t] = local;
    __syncthreads();
    for (int off = 1; off < 1024; off <<= 1) {
        unsigned v = scan[t] + ((t + off < 1024) ? scan[t + off] : 0u);
        __syncthreads();
        scan[t] = v;
        __syncthreads();
    }
    unsigned cum = scan[t] - local;   // count in bins strictly above this range
    if (NB >= 1024 || t < NB) {
        #pragma unroll
        for (int j = BPT - 1; j >= 0; j--) {
            int b = t * BPT + j;
            unsigned c = h[b];
            unsigned cg = cum + c;
            if (cg >= R && cum < R) { *outB = (unsigned)b; *outR = R - cum; }
            cum = cg;
        }
    }
    __syncthreads();
}

// ------------------------------------------------- fallback: pick bin
__global__ void fb_scan_kernel(int K) {
    if (g_fallback == 0) return;
    __shared__ unsigned h[BINS];
    __shared__ unsigned scan[1024];
    __shared__ unsigned outB, outR;
    int t = threadIdx.x;
    for (int i = t; i < BINS; i += 1024) h[i] = g_hist[i];
    __syncthreads();
    suffix_select<BINS>(h, scan, (unsigned)K, &outB, &outR);
    if (t == 0) g_binb = outB;
}

// ------------------------------------------------- fallback: compact by bin
__global__ void fb_compact_kernel(const float4* __restrict__ x4, int n4,
                                  const float* __restrict__ x, int n) {
    if (g_fallback == 0) return;
    unsigned b = g_binb;
    int t = blockIdx.x * blockDim.x + threadIdx.x;
    int stride = gridDim.x * blockDim.x;
    int lane = threadIdx.x & 31;
    for (int i = t; i < n4; i += stride) {
        float4 v = x4[i];
        bool p0 = (fkey(v.x) >> 20) >= b;
        bool p1 = (fkey(v.y) >> 20) >= b;
        bool p2 = (fkey(v.z) >> 20) >= b;
        bool p3 = (fkey(v.w) >> 20) >= b;
        int cnt = (int)p0 + (int)p1 + (int)p2 + (int)p3;
        if (!__ballot_sync(FULLMASK, cnt > 0)) continue;
        int pre = cnt;
        #pragma unroll
        for (int o = 1; o < 32; o <<= 1) {
            int u = __shfl_up_sync(FULLMASK, pre, o);
            if (lane >= o) pre += u;
        }
        int tot = __shfl_sync(FULLMASK, pre, 31);
        int base = 0;
        if (lane == 31) base = (int)atomicAdd(&g_cand_count, (unsigned)tot);
        base = __shfl_sync(FULLMASK, base, 31);
        int off = base + pre - cnt;
        int bi = i * 4;
        if (p0) { if (off < CAP) { g_cand_val[off] = v.x; g_cand_idx[off] = bi;     } off++; }
        if (p1) { if (off < CAP) { g_cand_val[off] = v.y; g_cand_idx[off] = bi + 1; } off++; }
        if (p2) { if (off < CAP) { g_cand_val[off] = v.z; g_cand_idx[off] = bi + 2; } off++; }
        if (p3) { if (off < CAP) { g_cand_val[off] = v.w; g_cand_idx[off] = bi + 3; } off++; }
    }
    if (blockIdx.x == 0 && (int)threadIdx.x < (n - n4 * 4)) {
        int idx = n4 * 4 + threadIdx.x;
        float f = x[idx];
        if ((fkey(f) >> 20) >= b) {
            unsigned off = atomicAdd(&g_cand_count, 1u);
            if (off < CAP) { g_cand_val[off] = f; g_cand_idx[off] = idx; }
        }
    }
}

// ------------------------------------------------- exact selection (1 block)
__global__ void select_kernel(int K) {
    __shared__ unsigned h[BINS];
    __shared__ unsigned scan[1024];
    __shared__ unsigned sB, sR;
    __shared__ unsigned sB1, sR1, sB2, sR2, sB3, sK3;
    __shared__ unsigned sTK;
    __shared__ unsigned sTieCount;
    __shared__ int      sTieThresh;
    int t = threadIdx.x;
    unsigned cc = g_cand_count;
    int M = (int)(cc < (unsigned)CAP ? cc : (unsigned)CAP);

    // ---- level 1: top 12 bits
    for (int i = t; i < BINS; i += 1024) h[i] = 0;
    __syncthreads();
    for (int i = t; i < M; i += 1024) atomicAdd(&h[fkey(g_cand_val[i]) >> 20], 1u);
    __syncthreads();
    suffix_select<BINS>(h, scan, (unsigned)K, &sB, &sR);
    if (t == 0) { sB1 = sB; sR1 = sR; }
    __syncthreads();
    unsigned B1 = sB1, R1 = sR1;

    // ---- level 2: bits 19..8
    for (int i = t; i < BINS; i += 1024) h[i] = 0;
    __syncthreads();
    for (int i = t; i < M; i += 1024) {
        unsigned k = fkey(g_cand_val[i]);
        if ((k >> 20) == B1) atomicAdd(&h[(k >> 8) & 0xFFFu], 1u);
    }
    __syncthreads();
    suffix_select<BINS>(h, scan, R1, &sB, &sR);
    if (t == 0) { sB2 = sB; sR2 = sR; }
    __syncthreads();
    unsigned B2 = sB2, R2 = sR2;
    unsigned top24 = (B1 << 12) | B2;

    // ---- level 3: bits 7..0
    for (int i = t; i < 256; i += 1024) h[i] = 0;
    __syncthreads();
    for (int i = t; i < M; i += 1024) {
        unsigned k = fkey(g_cand_val[i]);
        if ((k >> 8) == top24) atomicAdd(&h[k & 0xFFu], 1u);
    }
    __syncthreads();
    suffix_select<256>(h, scan, R2, &sB, &sR);
    if (t == 0) {
        sB3 = sB; sK3 = sR;
        sTK = (B1 << 20) | (B2 << 8) | sB;
        sTieCount = 0;
        sTieThresh = -1;
    }
    __syncthreads();
    unsigned TK = sTK, K3 = sK3;

    // ---- collect ties (key == TK)
    for (int i = t; i < M; i += 1024) {
        if (fkey(g_cand_val[i]) == TK) {
            unsigned p = atomicAdd(&sTieCount, 1u);
            if (p < (unsigned)TIECAP) g_tie_idx[p] = g_cand_idx[i];
        }
    }
    __syncthreads();
    int T = (int)(sTieCount < (unsigned)TIECAP ? sTieCount : (unsigned)TIECAP);
    // tie-break: select the K3 smallest indices among ties.
    for (int i = t; i < T; i += 1024) {
        int mi = g_tie_idx[i];
        int r = 0;
        for (int j = 0; j < T; j++) r += (int)(g_tie_idx[j] < mi);
        if (r == (int)K3 - 1) sTieThresh = mi;
    }
    __syncthreads();
    int tieThresh = sTieThresh;

    // ---- compact selected (exactly K)
    for (int i = t; i < M; i += 1024) {
        float v = g_cand_val[i];
        unsigned k = fkey(v);
        bool sel = (k > TK) || (k == TK && g_cand_idx[i] <= tieThresh);
        if (sel) {
            unsigned p = atomicAdd(&g_sel_count, 1u);
            if (p < 8192u) { g_sel_val[p] = v; g_sel_idx[p] = g_cand_idx[i]; }
        }
    }
}

// ------------------------------------------------- order by index, write out
__global__ void poswrite_kernel(float* __restrict__ out, int K) {
    __shared__ int sidx[8192];
    for (int i = threadIdx.x; i < K; i += blockDim.x) sidx[i] = g_sel_idx[i];
    __syncthreads();
    int i = blockIdx.x * blockDim.x + threadIdx.x;
    if (i >= K) return;
    int mi = sidx[i];
    int pos = 0;
    for (int j = 0; j < K; j++) pos += (int)(sidx[j] < mi);
    out[pos] = g_sel_val[i];
}

extern "C" void kernel_launch(void* const* d_in, const int* in_sizes, int n_in,
                              void* d_out, int out_size) {
    const float* x = (const float*)d_in[0];
    int n = in_sizes[0];
    int n4 = n / 4;
    const float4* x4 = (const float4*)x;
    int K = out_size;   // 5000
    float* out = (float*)d_out;

    static bool attr_set = false;
    if (!attr_set) {
        cudaFuncSetAttribute(poswrite_kernel,
                             cudaFuncAttributeMaxDynamicSharedMemorySize, 0);
        attr_set = true;
    }

    init_kernel<<<1, 1024>>>();
    spec_compact_kernel<<<296, 1024>>>(x4, n4, x, n);
    check_kernel<<<1, 1>>>(K);
    fb_hist_kernel<<<296, 1024>>>(x4, n4, x, n);
    fb_scan_kernel<<<1, 1024>>>(K);
    fb_compact_kernel<<<296, 1024>>>(x4, n4, x, n);
    select_kernel<<<1, 1024>>>(K);
    poswrite_kernel<<<(K + 255) / 256, 256>>>(out, K);
}

// round 3
// speedup vs baseline: 14.5437x; 1.3159x over previous
#include <cuda_runtime.h>

// Top-K (K=5000) of 50M floats, values output in original-index order.
//
// Fast path: streaming compaction of x >= 3.5 (~11.6K candidates for N(0,1)),
// then ONE block copies candidates to smem and does exact 32-bit radix
// selection (12+12+8 bits) + index tie-break there. Final small kernel orders
// the K selected values by original index via counting.
//
// Flag-guarded fallback (no-op normally): hist -> bin threshold -> re-compact
// guarantees correctness for arbitrary inputs.

#define CAP      (1 << 21)      // global candidate capacity
#define SMCAP    16384          // candidates held in smem by select_kernel
#define TIECAP   4096
#define BINS     4096
#define SPEC_VAL 3.5f
#define FULLMASK 0xFFFFFFFFu

__device__ unsigned g_hist[BINS];
__device__ unsigned g_cand_count;
__device__ unsigned g_fallback;
__device__ unsigned g_binb;
__device__ float    g_cand_val[CAP];
__device__ int      g_cand_idx[CAP];
__device__ unsigned g_sel_count;
__device__ float    g_sel_val[8192];
__device__ int      g_sel_idx[8192];

__device__ __forceinline__ unsigned fkey(float f) {
    unsigned u = __float_as_uint(f);
    return (u & 0x80000000u) ? ~u : (u | 0x80000000u);
}

// ---------------------------------------------------------------- init
__global__ void init_kernel() {
    int t = threadIdx.x;
    for (int i = t; i < BINS; i += 256) g_hist[i] = 0;
    if (t == 0) { g_cand_count = 0; g_fallback = 0; g_sel_count = 0; g_binb = 0; }
}

// ---------------------------------------------------- warp-aggregated emit
__device__ __forceinline__ void emit4(bool p0, bool p1, bool p2, bool p3,
                                      float4 v, int bi, int lane) {
    int cnt = (int)p0 + (int)p1 + (int)p2 + (int)p3;
    if (!__ballot_sync(FULLMASK, cnt > 0)) return;
    int pre = cnt;
    #pragma unroll
    for (int o = 1; o < 32; o <<= 1) {
        int u = __shfl_up_sync(FULLMASK, pre, o);
        if (lane >= o) pre += u;
    }
    int tot = __shfl_sync(FULLMASK, pre, 31);
    int base = 0;
    if (lane == 31) base = (int)atomicAdd(&g_cand_count, (unsigned)tot);
    base = __shfl_sync(FULLMASK, base, 31);
    int off = base + pre - cnt;
    if (p0) { if (off < CAP) { g_cand_val[off] = v.x; g_cand_idx[off] = bi;     } off++; }
    if (p1) { if (off < CAP) { g_cand_val[off] = v.y; g_cand_idx[off] = bi + 1; } off++; }
    if (p2) { if (off < CAP) { g_cand_val[off] = v.z; g_cand_idx[off] = bi + 2; } off++; }
    if (p3) { if (off < CAP) { g_cand_val[off] = v.w; g_cand_idx[off] = bi + 3; } off++; }
}

// ------------------------------------------------- pass 1: speculative compact
__global__ void spec_compact_kernel(const float4* __restrict__ x4, int n4,
                                    const float* __restrict__ x, int n) {
    int t = blockIdx.x * blockDim.x + threadIdx.x;
    int stride = gridDim.x * blockDim.x;
    int lane = threadIdx.x & 31;
    for (int i = t; i < n4; i += stride) {
        float4 v = x4[i];
        emit4(v.x >= SPEC_VAL, v.y >= SPEC_VAL, v.z >= SPEC_VAL, v.w >= SPEC_VAL,
              v, i * 4, lane);
    }
    if (blockIdx.x == 0 && (int)threadIdx.x < (n - n4 * 4)) {
        int idx = n4 * 4 + threadIdx.x;
        float f = x[idx];
        if (f >= SPEC_VAL) {
            unsigned off = atomicAdd(&g_cand_count, 1u);
            if (off < CAP) { g_cand_val[off] = f; g_cand_idx[off] = idx; }
        }
    }
}

// ------------------------------------------------- check speculation
__global__ void check_kernel(int K) {
    unsigned c = g_cand_count;
    if (c >= (unsigned)K && c <= (unsigned)CAP) {
        g_fallback = 0;
    } else {
        g_fallback = 1;
        g_cand_count = 0;
    }
}

// ------------------------------------------------- fallback: full histogram
__global__ void fb_hist_kernel(const float4* __restrict__ x4, int n4,
                               const float* __restrict__ x, int n) {
    if (g_fallback == 0) return;
    __shared__ unsigned sh[BINS];
    for (int i = threadIdx.x; i < BINS; i += blockDim.x) sh[i] = 0;
    __syncthreads();
    int t = blockIdx.x * blockDim.x + threadIdx.x;
    int stride = gridDim.x * blockDim.x;
    for (int i = t; i < n4; i += stride) {
        float4 v = x4[i];
        atomicAdd(&sh[fkey(v.x) >> 20], 1u);
        atomicAdd(&sh[fkey(v.y) >> 20], 1u);
        atomicAdd(&sh[fkey(v.z) >> 20], 1u);
        atomicAdd(&sh[fkey(v.w) >> 20], 1u);
    }
    if (blockIdx.x == 0 && (int)threadIdx.x < (n - n4 * 4)) {
        atomicAdd(&sh[fkey(x[n4 * 4 + threadIdx.x]) >> 20], 1u);
    }
    __syncthreads();
    for (int i = threadIdx.x; i < BINS; i += blockDim.x) {
        unsigned c = sh[i];
        if (c) atomicAdd(&g_hist[i], c);
    }
}

// suffix-select over smem hist (1024 threads): find bin B with
// cnt_ge(B) >= R > cnt_ge(B+1); write B and residual rank R-cnt_gt(B).
template <int NB>
__device__ void suffix_select(unsigned* h, unsigned* scan, unsigned R,
                              unsigned* outB, unsigned* outR) {
    const int BPT = (NB >= 1024) ? NB / 1024 : 1;
    int t = threadIdx.x;
    unsigned local = 0;
    if (NB >= 1024) {
        #pragma unroll
        for (int j = 0; j < BPT; j++) local += h[t * BPT + j];
    } else {
        local = (t < NB) ? h[t] : 0u;
    }
    scan[t] = local;
    __syncthreads();
    for (int off = 1; off < 1024; off <<= 1) {
        unsigned v = scan[t] + ((t + off < 1024) ? scan[t + off] : 0u);
        __syncthreads();
        scan[t] = v;
        __syncthreads();
    }
    unsigned cum = scan[t] - local;   // strictly above this thread's range
    if (NB >= 1024 || t < NB) {
        #pragma unroll
        for (int j = BPT - 1; j >= 0; j--) {
            int b = t * BPT + j;
            unsigned c = h[b];
            unsigned cg = cum + c;
            if (cg >= R && cum < R) { *outB = (unsigned)b; *outR = R - cum; }
            cum = cg;
        }
    }
    __syncthreads();
}

// ------------------------------------------------- fallback: pick bin
__global__ void fb_scan_kernel(int K) {
    if (g_fallback == 0) return;
    __shared__ unsigned h[BINS];
    __shared__ unsigned scan[1024];
    __shared__ unsigned outB, outR;
    int t = threadIdx.x;
    for (int i = t; i < BINS; i += 1024) h[i] = g_hist[i];
    __syncthreads();
    suffix_select<BINS>(h, scan, (unsigned)K, &outB, &outR);
    if (t == 0) g_binb = outB;
}

// ------------------------------------------------- fallback: compact by bin
__global__ void fb_compact_kernel(const float4* __restrict__ x4, int n4,
                                  const float* __restrict__ x, int n) {
    if (g_fallback == 0) return;
    unsigned b = g_binb;
    int t = blockIdx.x * blockDim.x + threadIdx.x;
    int stride = gridDim.x * blockDim.x;
    int lane = threadIdx.x & 31;
    for (int i = t; i < n4; i += stride) {
        float4 v = x4[i];
        emit4((fkey(v.x) >> 20) >= b, (fkey(v.y) >> 20) >= b,
              (fkey(v.z) >> 20) >= b, (fkey(v.w) >> 20) >= b, v, i * 4, lane);
    }
    if (blockIdx.x == 0 && (int)threadIdx.x < (n - n4 * 4)) {
        int idx = n4 * 4 + threadIdx.x;
        float f = x[idx];
        if ((fkey(f) >> 20) >= b) {
            unsigned off = atomicAdd(&g_cand_count, 1u);
            if (off < CAP) { g_cand_val[off] = f; g_cand_idx[off] = idx; }
        }
    }
}

// ------------------------------------------------- exact selection (1 block)
// Dynamic smem layout: [SMCAP floats][SMCAP ints][BINS u32][1024 u32 scan]
__global__ void select_kernel(int K) {
    extern __shared__ unsigned char dyn[];
    float*    sval = (float*)dyn;
    int*      sidx = (int*)(dyn + SMCAP * 4);
    unsigned* h    = (unsigned*)(dyn + SMCAP * 8);
    unsigned* scan = (unsigned*)(dyn + SMCAP * 8 + BINS * 4);

    __shared__ unsigned sB, sR;
    __shared__ unsigned sB1, sR1, sB2, sR2, sK3;
    __shared__ unsigned sTK;
    __shared__ unsigned sTieCount;
    __shared__ int      sTieIdx[TIECAP];
    __shared__ int      sTieThresh;

    int t = threadIdx.x;
    unsigned cc = g_cand_count;
    int M = (int)(cc < (unsigned)CAP ? cc : (unsigned)CAP);
    bool inSmem = (M <= SMCAP);

    const float* pv;
    const int*   pi;
    if (inSmem) {
        for (int i = t; i < M; i += 1024) { sval[i] = g_cand_val[i]; sidx[i] = g_cand_idx[i]; }
        __syncthreads();
        pv = sval; pi = sidx;
    } else {
        pv = g_cand_val; pi = g_cand_idx;
    }

    // ---- level 1: top 12 bits of key
    for (int i = t; i < BINS; i += 1024) h[i] = 0;
    __syncthreads();
    for (int i = t; i < M; i += 1024) atomicAdd(&h[fkey(pv[i]) >> 20], 1u);
    __syncthreads();
    suffix_select<BINS>(h, scan, (unsigned)K, &sB, &sR);
    if (t == 0) { sB1 = sB; sR1 = sR; }
    __syncthreads();
    unsigned B1 = sB1, R1 = sR1;

    // ---- level 2: bits 19..8
    for (int i = t; i < BINS; i += 1024) h[i] = 0;
    __syncthreads();
    for (int i = t; i < M; i += 1024) {
        unsigned k = fkey(pv[i]);
        if ((k >> 20) == B1) atomicAdd(&h[(k >> 8) & 0xFFFu], 1u);
    }
    __syncthreads();
    suffix_select<BINS>(h, scan, R1, &sB, &sR);
    if (t == 0) { sB2 = sB; sR2 = sR; }
    __syncthreads();
    unsigned B2 = sB2, R2 = sR2;
    unsigned top24 = (B1 << 12) | B2;

    // ---- level 3: bits 7..0
    for (int i = t; i < 256; i += 1024) h[i] = 0;
    __syncthreads();
    for (int i = t; i < M; i += 1024) {
        unsigned k = fkey(pv[i]);
        if ((k >> 8) == top24) atomicAdd(&h[k & 0xFFu], 1u);
    }
    __syncthreads();
    suffix_select<256>(h, scan, R2, &sB, &sR);
    if (t == 0) {
        sK3 = sR;
        sTK = (B1 << 20) | (B2 << 8) | sB;
        sTieCount = 0;
        sTieThresh = -1;
    }
    __syncthreads();
    unsigned TK = sTK, K3 = sK3;

    // ---- collect indices tied at the exact K-th key
    for (int i = t; i < M; i += 1024) {
        if (fkey(pv[i]) == TK) {
            unsigned p = atomicAdd(&sTieCount, 1u);
            if (p < (unsigned)TIECAP) sTieIdx[p] = pi[i];
        }
    }
    __syncthreads();
    int T = (int)(sTieCount < (unsigned)TIECAP ? sTieCount : (unsigned)TIECAP);
    // tie-break: keep the K3 smallest indices among ties; find the cutoff index
    for (int i = t; i < T; i += 1024) {
        int mi = sTieIdx[i];
        int r = 0;
        for (int j = 0; j < T; j++) r += (int)(sTieIdx[j] < mi);
        if (r == (int)K3 - 1) sTieThresh = mi;
    }
    __syncthreads();
    int tieThresh = sTieThresh;

    // ---- compact selected (exactly K) to global
    for (int i = t; i < M; i += 1024) {
        float v = pv[i];
        unsigned k = fkey(v);
        bool sel = (k > TK) || (k == TK && pi[i] <= tieThresh);
        if (sel) {
            unsigned p = atomicAdd(&g_sel_count, 1u);
            if (p < 8192u) { g_sel_val[p] = v; g_sel_idx[p] = pi[i]; }
        }
    }
}

// ------------------------------------------------- order by index, write out
__global__ void poswrite_kernel(float* __restrict__ out, int K) {
    __shared__ int sidx[8192];
    for (int i = threadIdx.x; i < K; i += blockDim.x) sidx[i] = g_sel_idx[i];
    __syncthreads();
    int i = blockIdx.x * blockDim.x + threadIdx.x;
    if (i >= K) return;
    int mi = sidx[i];
    int pos = 0;
    for (int j = 0; j < K; j++) pos += (int)(sidx[j] < mi);
    out[pos] = g_sel_val[i];
}

extern "C" void kernel_launch(void* const* d_in, const int* in_sizes, int n_in,
                              void* d_out, int out_size) {
    const float* x = (const float*)d_in[0];
    int n = in_sizes[0];
    int n4 = n / 4;
    const float4* x4 = (const float4*)x;
    int K = out_size;   // 5000
    float* out = (float*)d_out;

    const int SELECT_SMEM = SMCAP * 8 + BINS * 4 + 1024 * 4;  // 148 KB
    cudaFuncSetAttribute(select_kernel,
                         cudaFuncAttributeMaxDynamicSharedMemorySize, SELECT_SMEM);

    init_kernel<<<1, 256>>>();
    spec_compact_kernel<<<296, 1024>>>(x4, n4, x, n);
    check_kernel<<<1, 1>>>(K);
    fb_hist_kernel<<<148, 256>>>(x4, n4, x, n);
    fb_scan_kernel<<<1, 1024>>>(K);
    fb_compact_kernel<<<148, 256>>>(x4, n4, x, n);
    select_kernel<<<1, 1024, SELECT_SMEM>>>(K);
    poswrite_kernel<<<(K + 255) / 256, 256>>>(out, K);
}

// round 4
// speedup vs baseline: 23.0937x; 1.5879x over previous
#include <cuda_runtime.h>

// Top-K (K=5000) of 50M floats, values output in original-index order.
//
// Fast path: streaming compaction of x >= 3.5 (~11.6K candidates for N(0,1),
// 4-way unrolled loads for MLP), one-block exact 32-bit radix selection
// (12+12+8) with index tie-break in smem, then chunked index-rank ordering.
//
// Fallback (never runs on in-range data, speed irrelevant): ONE single-block
// kernel does full histogram -> threshold bin -> re-compact, guaranteeing
// correctness for arbitrary inputs at ~1us idle cost.

#define CAP      (1 << 21)      // global candidate capacity
#define SMCAP    16384          // candidates held in smem by select_kernel
#define TIECAP   4096
#define BINS     4096
#define SPEC_VAL 3.5f
#define FULLMASK 0xFFFFFFFFu
#define NEG_INF  (-3.402823466e38f)

__device__ unsigned g_cand_count;
__device__ float    g_cand_val[CAP];
__device__ int      g_cand_idx[CAP];
__device__ unsigned g_sel_count;
__device__ float    g_sel_val[8192];
__device__ int      g_sel_idx[8192];
__device__ int      g_pos[8192];

__device__ __forceinline__ unsigned fkey(float f) {
    unsigned u = __float_as_uint(f);
    return (u & 0x80000000u) ? ~u : (u | 0x80000000u);
}

// ---------------------------------------------------------------- init
__global__ void init_kernel() {
    int t = threadIdx.x;
    for (int i = t; i < 8192; i += 1024) g_pos[i] = 0;
    if (t == 0) { g_cand_count = 0; g_sel_count = 0; }
}

// ---------------------------------------------------- warp-aggregated emit
__device__ __forceinline__ void emit4(bool p0, bool p1, bool p2, bool p3,
                                      float4 v, int bi, int lane) {
    int cnt = (int)p0 + (int)p1 + (int)p2 + (int)p3;
    if (!__ballot_sync(FULLMASK, cnt > 0)) return;
    int pre = cnt;
    #pragma unroll
    for (int o = 1; o < 32; o <<= 1) {
        int u = __shfl_up_sync(FULLMASK, pre, o);
        if (lane >= o) pre += u;
    }
    int tot = __shfl_sync(FULLMASK, pre, 31);
    int base = 0;
    if (lane == 31) base = (int)atomicAdd(&g_cand_count, (unsigned)tot);
    base = __shfl_sync(FULLMASK, base, 31);
    int off = base + pre - cnt;
    if (p0) { if (off < CAP) { g_cand_val[off] = v.x; g_cand_idx[off] = bi;     } off++; }
    if (p1) { if (off < CAP) { g_cand_val[off] = v.y; g_cand_idx[off] = bi + 1; } off++; }
    if (p2) { if (off < CAP) { g_cand_val[off] = v.z; g_cand_idx[off] = bi + 2; } off++; }
    if (p3) { if (off < CAP) { g_cand_val[off] = v.w; g_cand_idx[off] = bi + 3; } off++; }
}

// ------------------------------------------------- pass 1: speculative compact
// 4 outstanding LDG.128 per thread per iteration to cover DRAM latency.
__global__ void spec_compact_kernel(const float4* __restrict__ x4, int n4,
                                    const float* __restrict__ x, int n) {
    int t = blockIdx.x * blockDim.x + threadIdx.x;
    int stride = gridDim.x * blockDim.x;
    int lane = threadIdx.x & 31;
    int iters = (n4 + stride - 1) / stride;    // uniform across all threads

    const float4 sent = make_float4(NEG_INF, NEG_INF, NEG_INF, NEG_INF);
    for (int k = 0; k < iters; k += 4) {
        int i0 = t + (k    ) * stride;
        int i1 = t + (k + 1) * stride;
        int i2 = t + (k + 2) * stride;
        int i3 = t + (k + 3) * stride;
        float4 a = (i0 < n4) ? x4[i0] : sent;
        float4 b = (i1 < n4) ? x4[i1] : sent;
        float4 c = (i2 < n4) ? x4[i2] : sent;
        float4 d = (i3 < n4) ? x4[i3] : sent;
        float m = fmaxf(fmaxf(fmaxf(a.x, a.y), fmaxf(a.z, a.w)),
                        fmaxf(fmaxf(b.x, b.y), fmaxf(b.z, b.w)));
        m = fmaxf(m, fmaxf(fmaxf(fmaxf(c.x, c.y), fmaxf(c.z, c.w)),
                           fmaxf(fmaxf(d.x, d.y), fmaxf(d.z, d.w))));
        if (__ballot_sync(FULLMASK, m >= SPEC_VAL)) {
            emit4(a.x >= SPEC_VAL, a.y >= SPEC_VAL, a.z >= SPEC_VAL, a.w >= SPEC_VAL, a, i0 * 4, lane);
            emit4(b.x >= SPEC_VAL, b.y >= SPEC_VAL, b.z >= SPEC_VAL, b.w >= SPEC_VAL, b, i1 * 4, lane);
            emit4(c.x >= SPEC_VAL, c.y >= SPEC_VAL, c.z >= SPEC_VAL, c.w >= SPEC_VAL, c, i2 * 4, lane);
            emit4(d.x >= SPEC_VAL, d.y >= SPEC_VAL, d.z >= SPEC_VAL, d.w >= SPEC_VAL, d, i3 * 4, lane);
        }
    }
    // scalar tail (n % 4 elements)
    if (blockIdx.x == 0 && (int)threadIdx.x < (n - n4 * 4)) {
        int idx = n4 * 4 + threadIdx.x;
        float f = x[idx];
        if (f >= SPEC_VAL) {
            unsigned off = atomicAdd(&g_cand_count, 1u);
            if (off < CAP) { g_cand_val[off] = f; g_cand_idx[off] = idx; }
        }
    }
}

// suffix-select over smem hist (1024 threads): find bin B with
// cnt_ge(B) >= R > cnt_ge(B+1); write B and residual rank R-cnt_gt(B).
template <int NB>
__device__ void suffix_select(unsigned* h, unsigned* scan, unsigned R,
                              unsigned* outB, unsigned* outR) {
    const int BPT = (NB >= 1024) ? NB / 1024 : 1;
    int t = threadIdx.x;
    unsigned local = 0;
    if (NB >= 1024) {
        #pragma unroll
        for (int j = 0; j < BPT; j++) local += h[t * BPT + j];
    } else {
        local = (t < NB) ? h[t] : 0u;
    }
    scan[t] = local;
    __syncthreads();
    for (int off = 1; off < 1024; off <<= 1) {
        unsigned v = scan[t] + ((t + off < 1024) ? scan[t + off] : 0u);
        __syncthreads();
        scan[t] = v;
        __syncthreads();
    }
    unsigned cum = scan[t] - local;   // strictly above this thread's range
    if (NB >= 1024 || t < NB) {
        #pragma unroll
        for (int j = BPT - 1; j >= 0; j--) {
            int b = t * BPT + j;
            unsigned c = h[b];
            unsigned cg = cum + c;
            if (cg >= R && cum < R) { *outB = (unsigned)b; *outR = R - cum; }
            cum = cg;
        }
    }
    __syncthreads();
}

// ------------------------------------------------- fallback (single block)
// Only activates if speculation failed (count < K or > CAP). Slow but correct;
// idle cost is ~1us.
__global__ void fallback_kernel(const float4* __restrict__ x4, int n4,
                                const float* __restrict__ x, int n, int K) {
    unsigned cc = g_cand_count;
    if (cc >= (unsigned)K && cc <= (unsigned)CAP) return;   // uniform branch

    __shared__ unsigned h[BINS];
    __shared__ unsigned scan[1024];
    __shared__ unsigned outB, outR;
    int t = threadIdx.x;
    for (int i = t; i < BINS; i += 1024) h[i] = 0;
    __syncthreads();
    for (int i = t; i < n4; i += 1024) {
        float4 v = x4[i];
        atomicAdd(&h[fkey(v.x) >> 20], 1u);
        atomicAdd(&h[fkey(v.y) >> 20], 1u);
        atomicAdd(&h[fkey(v.z) >> 20], 1u);
        atomicAdd(&h[fkey(v.w) >> 20], 1u);
    }
    for (int i = n4 * 4 + t; i < n; i += 1024)
        atomicAdd(&h[fkey(x[i]) >> 20], 1u);
    __syncthreads();
    suffix_select<BINS>(h, scan, (unsigned)K, &outB, &outR);
    if (t == 0) g_cand_count = 0;
    __syncthreads();
    unsigned b = outB;
    for (int i = t; i < n; i += 1024) {
        float f = x[i];
        if ((fkey(f) >> 20) >= b) {
            unsigned off = atomicAdd(&g_cand_count, 1u);
            if (off < CAP) { g_cand_val[off] = f; g_cand_idx[off] = i; }
        }
    }
}

// ------------------------------------------------- exact selection (1 block)
// Dynamic smem layout: [SMCAP floats][SMCAP ints][BINS u32][1024 u32 scan]
__global__ void select_kernel(int K) {
    extern __shared__ unsigned char dyn[];
    float*    sval = (float*)dyn;
    int*      sidx = (int*)(dyn + SMCAP * 4);
    unsigned* h    = (unsigned*)(dyn + SMCAP * 8);
    unsigned* scan = (unsigned*)(dyn + SMCAP * 8 + BINS * 4);

    __shared__ unsigned sB, sR;
    __shared__ unsigned sB1, sR1, sB2, sR2, sK3;
    __shared__ unsigned sTK;
    __shared__ unsigned sTieCount;
    __shared__ int      sTieIdx[TIECAP];
    __shared__ int      sTieThresh;

    int t = threadIdx.x;
    unsigned cc = g_cand_count;
    int M = (int)(cc < (unsigned)CAP ? cc : (unsigned)CAP);
    bool inSmem = (M <= SMCAP);

    const float* pv;
    const int*   pi;
    if (inSmem) {
        for (int i = t; i < M; i += 1024) { sval[i] = g_cand_val[i]; sidx[i] = g_cand_idx[i]; }
        __syncthreads();
        pv = sval; pi = sidx;
    } else {
        pv = g_cand_val; pi = g_cand_idx;
    }

    // ---- level 1: top 12 bits of key
    for (int i = t; i < BINS; i += 1024) h[i] = 0;
    __syncthreads();
    for (int i = t; i < M; i += 1024) atomicAdd(&h[fkey(pv[i]) >> 20], 1u);
    __syncthreads();
    suffix_select<BINS>(h, scan, (unsigned)K, &sB, &sR);
    if (t == 0) { sB1 = sB; sR1 = sR; }
    __syncthreads();
    unsigned B1 = sB1, R1 = sR1;

    // ---- level 2: bits 19..8
    for (int i = t; i < BINS; i += 1024) h[i] = 0;
    __syncthreads();
    for (int i = t; i < M; i += 1024) {
        unsigned k = fkey(pv[i]);
        if ((k >> 20) == B1) atomicAdd(&h[(k >> 8) & 0xFFFu], 1u);
    }
    __syncthreads();
    suffix_select<BINS>(h, scan, R1, &sB, &sR);
    if (t == 0) { sB2 = sB; sR2 = sR; }
    __syncthreads();
    unsigned B2 = sB2, R2 = sR2;
    unsigned top24 = (B1 << 12) | B2;

    // ---- level 3: bits 7..0
    for (int i = t; i < 256; i += 1024) h[i] = 0;
    __syncthreads();
    for (int i = t; i < M; i += 1024) {
        unsigned k = fkey(pv[i]);
        if ((k >> 8) == top24) atomicAdd(&h[k & 0xFFu], 1u);
    }
    __syncthreads();
    suffix_select<256>(h, scan, R2, &sB, &sR);
    if (t == 0) {
        sK3 = sR;
        sTK = (B1 << 20) | (B2 << 8) | sB;
        sTieCount = 0;
        sTieThresh = -1;
    }
    __syncthreads();
    unsigned TK = sTK, K3 = sK3;

    // ---- collect indices tied at the exact K-th key
    for (int i = t; i < M; i += 1024) {
        if (fkey(pv[i]) == TK) {
            unsigned p = atomicAdd(&sTieCount, 1u);
            if (p < (unsigned)TIECAP) sTieIdx[p] = pi[i];
        }
    }
    __syncthreads();
    int T = (int)(sTieCount < (unsigned)TIECAP ? sTieCount : (unsigned)TIECAP);
    // tie-break: keep the K3 smallest indices among ties; find the cutoff index
    for (int i = t; i < T; i += 1024) {
        int mi = sTieIdx[i];
        int r = 0;
        for (int j = 0; j < T; j++) r += (int)(sTieIdx[j] < mi);
        if (r == (int)K3 - 1) sTieThresh = mi;
    }
    __syncthreads();
    int tieThresh = sTieThresh;

    // ---- compact selected (exactly K) to global
    for (int i = t; i < M; i += 1024) {
        float v = pv[i];
        unsigned k = fkey(v);
        bool sel = (k > TK) || (k == TK && pi[i] <= tieThresh);
        if (sel) {
            unsigned p = atomicAdd(&g_sel_count, 1u);
            if (p < 8192u) { g_sel_val[p] = v; g_sel_idx[p] = pi[i]; }
        }
    }
}

// -------------------------------------------- pos[i] = rank of idx among sel
// Tasks: (i, chunk); consecutive threads share chunk -> broadcast inner reads.
__global__ void pos_kernel(int K) {
    int nch = (K + 255) / 256;
    int total = K * nch;
    int s = blockIdx.x * blockDim.x + threadIdx.x;
    if (s >= total) return;
    int c = s / K;
    int i = s - c * K;
    int mi = g_sel_idx[i];
    int j0 = c * 256;
    int j1 = j0 + 256; if (j1 > K) j1 = K;
    int r = 0;
    for (int j = j0; j < j1; j++) r += (int)(g_sel_idx[j] < mi);
    if (r) atomicAdd(&g_pos[i], r);
}

__global__ void write_kernel(float* __restrict__ out, int K) {
    int i = blockIdx.x * blockDim.x + threadIdx.x;
    if (i < K) out[g_pos[i]] = g_sel_val[i];
}

extern "C" void kernel_launch(void* const* d_in, const int* in_sizes, int n_in,
                              void* d_out, int out_size) {
    const float* x = (const float*)d_in[0];
    int n = in_sizes[0];
    int n4 = n / 4;
    const float4* x4 = (const float4*)x;
    int K = out_size;   // 5000
    float* out = (float*)d_out;

    const int SELECT_SMEM = SMCAP * 8 + BINS * 4 + 1024 * 4;  // 148 KB
    cudaFuncSetAttribute(select_kernel,
                         cudaFuncAttributeMaxDynamicSharedMemorySize, SELECT_SMEM);

    init_kernel<<<1, 1024>>>();
    spec_compact_kernel<<<296, 1024>>>(x4, n4, x, n);
    fallback_kernel<<<1, 1024>>>(x4, n4, x, n, K);
    select_kernel<<<1, 1024, SELECT_SMEM>>>(K);
    int nch = (K + 255) / 256;
    pos_kernel<<<(K * nch + 255) / 256, 256>>>(K);
    write_kernel<<<(K + 255) / 256, 256>>>(out, K);
}

// round 5
// speedup vs baseline: 24.0116x; 1.0397x over previous
#include <cuda_runtime.h>

// Top-K (K=5000) of 50M floats, values output in original-index order.
//
// Fast path: streaming compaction of x >= 3.6 (~8K candidates for N(0,1));
// the streaming pass also builds the 4096-bin MSB-key histogram of candidates
// (RED ops hidden under DRAM traffic). One block then does exact radix
// selection (levels 2+3 only) + index tie-break in smem; chunked index-rank
// ordering writes the output. write_kernel resets all state for graph replay.
//
// Fallback (never runs in-distribution; idle cost ~1us): one block recomputes
// a full 12-bit histogram, picks the threshold bin, recompacts.

#define CAP      (1 << 21)      // global candidate capacity
#define SMCAP    16384          // candidates held in smem by select_kernel
#define TIECAP   4096
#define BINS     4096
#define SPEC_VAL 3.6f
#define FULLMASK 0xFFFFFFFFu
#define NEG_INF  (-3.402823466e38f)

__device__ unsigned g_hist[BINS];
__device__ unsigned g_cand_count;
__device__ float    g_cand_val[CAP];
__device__ int      g_cand_idx[CAP];
__device__ unsigned g_sel_count;
__device__ float    g_sel_val[8192];
__device__ int      g_sel_idx[8192];
__device__ int      g_pos[8192];

__device__ __forceinline__ unsigned fkey(float f) {
    unsigned u = __float_as_uint(f);
    return (u & 0x80000000u) ? ~u : (u | 0x80000000u);
}

// ------------------------------------------ warp-aggregated emit + hist RED
__device__ __forceinline__ void emit4(bool p0, bool p1, bool p2, bool p3,
                                      float4 v, int bi, int lane) {
    int cnt = (int)p0 + (int)p1 + (int)p2 + (int)p3;
    if (!__ballot_sync(FULLMASK, cnt > 0)) return;
    int pre = cnt;
    #pragma unroll
    for (int o = 1; o < 32; o <<= 1) {
        int u = __shfl_up_sync(FULLMASK, pre, o);
        if (lane >= o) pre += u;
    }
    int tot = __shfl_sync(FULLMASK, pre, 31);
    int base = 0;
    if (lane == 31) base = (int)atomicAdd(&g_cand_count, (unsigned)tot);
    base = __shfl_sync(FULLMASK, base, 31);
    int off = base + pre - cnt;
    if (p0) { if (off < CAP) { g_cand_val[off] = v.x; g_cand_idx[off] = bi;
                               atomicAdd(&g_hist[fkey(v.x) >> 20], 1u); } off++; }
    if (p1) { if (off < CAP) { g_cand_val[off] = v.y; g_cand_idx[off] = bi + 1;
                               atomicAdd(&g_hist[fkey(v.y) >> 20], 1u); } off++; }
    if (p2) { if (off < CAP) { g_cand_val[off] = v.z; g_cand_idx[off] = bi + 2;
                               atomicAdd(&g_hist[fkey(v.z) >> 20], 1u); } off++; }
    if (p3) { if (off < CAP) { g_cand_val[off] = v.w; g_cand_idx[off] = bi + 3;
                               atomicAdd(&g_hist[fkey(v.w) >> 20], 1u); } off++; }
}

// ------------------------------------------------- pass 1: speculative compact
// 4 outstanding LDG.128 per thread per iteration to cover DRAM latency.
__global__ void spec_compact_kernel(const float4* __restrict__ x4, int n4,
                                    const float* __restrict__ x, int n) {
    int t = blockIdx.x * blockDim.x + threadIdx.x;
    int stride = gridDim.x * blockDim.x;
    int lane = threadIdx.x & 31;
    int iters = (n4 + stride - 1) / stride;    // uniform across all threads

    const float4 sent = make_float4(NEG_INF, NEG_INF, NEG_INF, NEG_INF);
    for (int k = 0; k < iters; k += 4) {
        int i0 = t + (k    ) * stride;
        int i1 = t + (k + 1) * stride;
        int i2 = t + (k + 2) * stride;
        int i3 = t + (k + 3) * stride;
        float4 a = (i0 < n4) ? x4[i0] : sent;
        float4 b = (i1 < n4) ? x4[i1] : sent;
        float4 c = (i2 < n4) ? x4[i2] : sent;
        float4 d = (i3 < n4) ? x4[i3] : sent;
        float m = fmaxf(fmaxf(fmaxf(a.x, a.y), fmaxf(a.z, a.w)),
                        fmaxf(fmaxf(b.x, b.y), fmaxf(b.z, b.w)));
        m = fmaxf(m, fmaxf(fmaxf(fmaxf(c.x, c.y), fmaxf(c.z, c.w)),
                           fmaxf(fmaxf(d.x, d.y), fmaxf(d.z, d.w))));
        if (__ballot_sync(FULLMASK, m >= SPEC_VAL)) {
            emit4(a.x >= SPEC_VAL, a.y >= SPEC_VAL, a.z >= SPEC_VAL, a.w >= SPEC_VAL, a, i0 * 4, lane);
            emit4(b.x >= SPEC_VAL, b.y >= SPEC_VAL, b.z >= SPEC_VAL, b.w >= SPEC_VAL, b, i1 * 4, lane);
            emit4(c.x >= SPEC_VAL, c.y >= SPEC_VAL, c.z >= SPEC_VAL, c.w >= SPEC_VAL, c, i2 * 4, lane);
            emit4(d.x >= SPEC_VAL, d.y >= SPEC_VAL, d.z >= SPEC_VAL, d.w >= SPEC_VAL, d, i3 * 4, lane);
        }
    }
    // scalar tail (n % 4 elements)
    if (blockIdx.x == 0 && (int)threadIdx.x < (n - n4 * 4)) {
        int idx = n4 * 4 + threadIdx.x;
        float f = x[idx];
        if (f >= SPEC_VAL) {
            unsigned off = atomicAdd(&g_cand_count, 1u);
            if (off < CAP) {
                g_cand_val[off] = f; g_cand_idx[off] = idx;
                atomicAdd(&g_hist[fkey(f) >> 20], 1u);
            }
        }
    }
}

// suffix-select over smem hist (1024 threads): find bin B with
// cnt_ge(B) >= R > cnt_ge(B+1); write B and residual rank R-cnt_gt(B).
template <int NB>
__device__ void suffix_select(unsigned* h, unsigned* scan, unsigned R,
                              unsigned* outB, unsigned* outR) {
    const int BPT = (NB >= 1024) ? NB / 1024 : 1;
    int t = threadIdx.x;
    unsigned local = 0;
    if (NB >= 1024) {
        #pragma unroll
        for (int j = 0; j < BPT; j++) local += h[t * BPT + j];
    } else {
        local = (t < NB) ? h[t] : 0u;
    }
    scan[t] = local;
    __syncthreads();
    for (int off = 1; off < 1024; off <<= 1) {
        unsigned v = scan[t] + ((t + off < 1024) ? scan[t + off] : 0u);
        __syncthreads();
        scan[t] = v;
        __syncthreads();
    }
    unsigned cum = scan[t] - local;   // strictly above this thread's range
    if (NB >= 1024 || t < NB) {
        #pragma unroll
        for (int j = BPT - 1; j >= 0; j--) {
            int b = t * BPT + j;
            unsigned c = h[b];
            unsigned cg = cum + c;
            if (cg >= R && cum < R) { *outB = (unsigned)b; *outR = R - cum; }
            cum = cg;
        }
    }
    __syncthreads();
}

// ------------------------------------------------- fallback (single block)
// Activates only if speculation failed (count < K or > CAP). Rebuilds g_hist
// to the full-data histogram (valid for select's level 1) and recompacts.
__global__ void fallback_kernel(const float4* __restrict__ x4, int n4,
                                const float* __restrict__ x, int n, int K) {
    unsigned cc = g_cand_count;
    if (cc >= (unsigned)K && cc <= (unsigned)CAP) return;   // uniform branch

    __shared__ unsigned h[BINS];
    __shared__ unsigned scan[1024];
    __shared__ unsigned outB, outR;
    int t = threadIdx.x;
    for (int i = t; i < BINS; i += 1024) h[i] = 0;
    __syncthreads();
    for (int i = t; i < n4; i += 1024) {
        float4 v = x4[i];
        atomicAdd(&h[fkey(v.x) >> 20], 1u);
        atomicAdd(&h[fkey(v.y) >> 20], 1u);
        atomicAdd(&h[fkey(v.z) >> 20], 1u);
        atomicAdd(&h[fkey(v.w) >> 20], 1u);
    }
    for (int i = n4 * 4 + t; i < n; i += 1024)
        atomicAdd(&h[fkey(x[i]) >> 20], 1u);
    __syncthreads();
    // overwrite polluted g_hist with the full-data histogram
    for (int i = t; i < BINS; i += 1024) g_hist[i] = h[i];
    suffix_select<BINS>(h, scan, (unsigned)K, &outB, &outR);
    if (t == 0) g_cand_count = 0;
    __syncthreads();
    unsigned b = outB;
    for (int i = t; i < n; i += 1024) {
        float f = x[i];
        if ((fkey(f) >> 20) >= b) {
            unsigned off = atomicAdd(&g_cand_count, 1u);
            if (off < CAP) { g_cand_val[off] = f; g_cand_idx[off] = i; }
        }
    }
}

// ------------------------------------------------- exact selection (1 block)
// Level 1 comes from the prebuilt g_hist; levels 2 (bits 19..8) and 3
// (bits 7..0) scan the smem-resident candidates.
// Dynamic smem layout: [SMCAP floats][SMCAP ints][BINS u32][1024 u32 scan]
__global__ void select_kernel(int K) {
    extern __shared__ unsigned char dyn[];
    float*    sval = (float*)dyn;
    int*      sidx = (int*)(dyn + SMCAP * 4);
    unsigned* h    = (unsigned*)(dyn + SMCAP * 8);
    unsigned* scan = (unsigned*)(dyn + SMCAP * 8 + BINS * 4);

    __shared__ unsigned sB, sR;
    __shared__ unsigned sB1, sR1, sB2, sR2, sK3;
    __shared__ unsigned sTK;
    __shared__ unsigned sTieCount;
    __shared__ int      sTieIdx[TIECAP];
    __shared__ int      sTieThresh;

    int t = threadIdx.x;
    unsigned cc = g_cand_count;
    int M = (int)(cc < (unsigned)CAP ? cc : (unsigned)CAP);
    bool inSmem = (M <= SMCAP);

    const float* pv;
    const int*   pi;
    // copy candidates to smem and load prebuilt level-1 histogram
    if (inSmem) {
        for (int i = t; i < M; i += 1024) { sval[i] = g_cand_val[i]; sidx[i] = g_cand_idx[i]; }
        pv = sval; pi = sidx;
    } else {
        pv = g_cand_val; pi = g_cand_idx;
    }
    for (int i = t; i < BINS; i += 1024) h[i] = g_hist[i];
    __syncthreads();

    // ---- level 1: prebuilt histogram of top 12 key bits
    suffix_select<BINS>(h, scan, (unsigned)K, &sB, &sR);
    if (t == 0) { sB1 = sB; sR1 = sR; }
    __syncthreads();
    unsigned B1 = sB1, R1 = sR1;

    // ---- level 2: bits 19..8
    for (int i = t; i < BINS; i += 1024) h[i] = 0;
    __syncthreads();
    for (int i = t; i < M; i += 1024) {
        unsigned k = fkey(pv[i]);
        if ((k >> 20) == B1) atomicAdd(&h[(k >> 8) & 0xFFFu], 1u);
    }
    __syncthreads();
    suffix_select<BINS>(h, scan, R1, &sB, &sR);
    if (t == 0) { sB2 = sB; sR2 = sR; }
    __syncthreads();
    unsigned B2 = sB2, R2 = sR2;
    unsigned top24 = (B1 << 12) | B2;

    // ---- level 3: bits 7..0
    for (int i = t; i < 256; i += 1024) h[i] = 0;
    __syncthreads();
    for (int i = t; i < M; i += 1024) {
        unsigned k = fkey(pv[i]);
        if ((k >> 8) == top24) atomicAdd(&h[k & 0xFFu], 1u);
    }
    __syncthreads();
    suffix_select<256>(h, scan, R2, &sB, &sR);
    if (t == 0) {
        sK3 = sR;
        sTK = (B1 << 20) | (B2 << 8) | sB;
        sTieCount = 0;
        sTieThresh = -1;
    }
    __syncthreads();
    unsigned TK = sTK, K3 = sK3;

    // ---- collect indices tied at the exact K-th key
    for (int i = t; i < M; i += 1024) {
        if (fkey(pv[i]) == TK) {
            unsigned p = atomicAdd(&sTieCount, 1u);
            if (p < (unsigned)TIECAP) sTieIdx[p] = pi[i];
        }
    }
    __syncthreads();
    int T = (int)(sTieCount < (unsigned)TIECAP ? sTieCount : (unsigned)TIECAP);
    // tie-break: keep the K3 smallest indices among ties; find the cutoff index
    for (int i = t; i < T; i += 1024) {
        int mi = sTieIdx[i];
        int r = 0;
        for (int j = 0; j < T; j++) r += (int)(sTieIdx[j] < mi);
        if (r == (int)K3 - 1) sTieThresh = mi;
    }
    __syncthreads();
    int tieThresh = sTieThresh;

    // ---- compact selected (exactly K) to global
    for (int i = t; i < M; i += 1024) {
        float v = pv[i];
        unsigned k = fkey(v);
        bool sel = (k > TK) || (k == TK && pi[i] <= tieThresh);
        if (sel) {
            unsigned p = atomicAdd(&g_sel_count, 1u);
            if (p < 8192u) { g_sel_val[p] = v; g_sel_idx[p] = pi[i]; }
        }
    }
}

// -------------------------------------------- pos[i] = rank of idx among sel
// Tasks: (i, chunk); consecutive threads share chunk -> broadcast inner reads.
__global__ void pos_kernel(int K) {
    int nch = (K + 255) / 256;
    int total = K * nch;
    int s = blockIdx.x * blockDim.x + threadIdx.x;
    if (s >= total) return;
    int c = s / K;
    int i = s - c * K;
    int mi = g_sel_idx[i];
    int j0 = c * 256;
    int j1 = j0 + 256; if (j1 > K) j1 = K;
    int r = 0;
    for (int j = j0; j < j1; j++) r += (int)(g_sel_idx[j] < mi);
    if (r) atomicAdd(&g_pos[i], r);
}

// ------------------------- write output and reset all state for next replay
__global__ void write_kernel(float* __restrict__ out, int K) {
    int t = blockIdx.x * blockDim.x + threadIdx.x;
    int stride = gridDim.x * blockDim.x;
    for (int i = t; i < K; i += stride) {
        out[g_pos[i]] = g_sel_val[i];
        g_pos[i] = 0;
    }
    for (int i = t; i < BINS; i += stride) g_hist[i] = 0;
    if (t == 0) { g_cand_count = 0; g_sel_count = 0; }
}

extern "C" void kernel_launch(void* const* d_in, const int* in_sizes, int n_in,
                              void* d_out, int out_size) {
    const float* x = (const float*)d_in[0];
    int n = in_sizes[0];
    int n4 = n / 4;
    const float4* x4 = (const float4*)x;
    int K = out_size;   // 5000
    float* out = (float*)d_out;

    const int SELECT_SMEM = SMCAP * 8 + BINS * 4 + 1024 * 4;  // 148 KB
    cudaFuncSetAttribute(select_kernel,
                         cudaFuncAttributeMaxDynamicSharedMemorySize, SELECT_SMEM);

    spec_compact_kernel<<<296, 1024>>>(x4, n4, x, n);
    fallback_kernel<<<1, 1024>>>(x4, n4, x, n, K);
    select_kernel<<<1, 1024, SELECT_SMEM>>>(K);
    int nch = (K + 255) / 256;
    pos_kernel<<<(K * nch + 255) / 256, 256>>>(K);
    write_kernel<<<(K + 255) / 256, 256>>>(out, K);
}